// round 3
// baseline (speedup 1.0000x reference)
#include <cuda_runtime.h>
#include <math_constants.h>

#define MAXN 131072
#define MAXB 32
#define EPSV 1e-5f

// ---------------- scratch (static device globals; no allocation) ----------------
__device__ float    g_mlp [256 * MAXN];   // mlp_feat [256][N]   (128 MB)
__device__ float    g_y2v [512 * MAXN];   // pre-BN2 y2 [512][N] (256 MB)
__device__ float    g_psum[512 * 1024];   // per-(c, n-block) partial sums
__device__ float    g_psq [512 * 1024];   // per-(c, n-block) partial sumsq
__device__ float    g_xpart[128 * 9];     // x-stats block partials
__device__ float    g_Wf1[128 * 3];       // folded conv1a*BN1 weights
__device__ float    g_bf1[128];
__device__ float    g_a2[512];            // folded BN2 scale
__device__ float    g_c2[512];            // folded BN2 shift
__device__ unsigned g_pool1u[MAXB * 256];
__device__ float    g_pool1 [MAXB * 256];
__device__ unsigned g_pool2u[MAXB * 1024];
__device__ int      g_off[MAXB + 1];

// monotonic float<->uint key for exact atomic max (handles negatives)
__device__ __forceinline__ unsigned fkey(float f) {
    unsigned u = __float_as_uint(f);
    return (u & 0x80000000u) ? ~u : (u | 0x80000000u);
}
__device__ __forceinline__ float funkey(unsigned k) {
    return (k & 0x80000000u) ? __uint_as_float(k & 0x7fffffffu)
                             : __uint_as_float(~k);
}

// ---------------- K0: offsets + pool init ----------------
__global__ void k_init(const int* npts, int B) {
    int tid = blockIdx.x * blockDim.x + threadIdx.x;
    if (blockIdx.x == 0 && threadIdx.x == 0) {
        int acc = 0; g_off[0] = 0;
        for (int b = 0; b < B; b++) { acc += npts[b]; g_off[b + 1] = acc; }
    }
    int stride = gridDim.x * blockDim.x;
    for (int i = tid; i < MAXB * 256;  i += stride) g_pool1u[i] = 0u;
    for (int i = tid; i < MAXB * 1024; i += stride) g_pool2u[i] = 0u;
}

// ---------------- K1a: x first/second moments (block partials) ----------------
__global__ void k_xstats(const float* __restrict__ x, int N) {
    float s0 = 0, s1 = 0, s2 = 0, q0 = 0, q1 = 0, q2 = 0, q3 = 0, q4 = 0, q5 = 0;
    int stride = gridDim.x * blockDim.x;
    for (int n = blockIdx.x * blockDim.x + threadIdx.x; n < N; n += stride) {
        float a = x[n], b = x[N + n], c = x[2 * N + n];
        s0 += a; s1 += b; s2 += c;
        q0 += a * a; q1 += a * b; q2 += a * c; q3 += b * b; q4 += b * c; q5 += c * c;
    }
    __shared__ float rb[256];
    float vals[9] = {s0, s1, s2, q0, q1, q2, q3, q4, q5};
    for (int v = 0; v < 9; v++) {
        rb[threadIdx.x] = vals[v];
        __syncthreads();
        for (int st = 128; st > 0; st >>= 1) {
            if (threadIdx.x < st) rb[threadIdx.x] += rb[threadIdx.x + st];
            __syncthreads();
        }
        if (threadIdx.x == 0) g_xpart[blockIdx.x * 9 + v] = rb[0];
        __syncthreads();
    }
}

// ---------------- K1b: fold BN1 into conv1a (analytic mean/var) ----------------
__global__ void k_fold1(const float* __restrict__ W1a, const float* __restrict__ b1a,
                        const float* __restrict__ g1,  const float* __restrict__ be1,
                        int N, int nblocks) {
    __shared__ double S[9];
    __shared__ float mu[3], C[3][3];
    if (threadIdx.x < 9) {
        double a = 0;
        for (int b = 0; b < nblocks; b++) a += (double)g_xpart[b * 9 + threadIdx.x];
        S[threadIdx.x] = a;
    }
    __syncthreads();
    if (threadIdx.x == 0) {
        double invN = 1.0 / (double)N;
        double m0 = S[0] * invN, m1 = S[1] * invN, m2 = S[2] * invN;
        mu[0] = (float)m0; mu[1] = (float)m1; mu[2] = (float)m2;
        C[0][0] = (float)(S[3] * invN - m0 * m0);
        C[0][1] = (float)(S[4] * invN - m0 * m1);
        C[0][2] = (float)(S[5] * invN - m0 * m2);
        C[1][1] = (float)(S[6] * invN - m1 * m1);
        C[1][2] = (float)(S[7] * invN - m1 * m2);
        C[2][2] = (float)(S[8] * invN - m2 * m2);
        C[1][0] = C[0][1]; C[2][0] = C[0][2]; C[2][1] = C[1][2];
    }
    __syncthreads();
    int c = threadIdx.x;  // 0..127
    float w0 = W1a[c * 3], w1 = W1a[c * 3 + 1], w2 = W1a[c * 3 + 2];
    float mean1 = w0 * mu[0] + w1 * mu[1] + w2 * mu[2] + b1a[c];
    float var1 = w0 * w0 * C[0][0] + w1 * w1 * C[1][1] + w2 * w2 * C[2][2]
               + 2.f * (w0 * w1 * C[0][1] + w0 * w2 * C[0][2] + w1 * w2 * C[1][2]);
    float a = g1[c] * rsqrtf(var1 + EPSV);
    g_Wf1[c * 3 + 0] = a * w0;
    g_Wf1[c * 3 + 1] = a * w1;
    g_Wf1[c * 3 + 2] = a * w2;
    g_bf1[c] = a * (b1a[c] - mean1) + be1[c];
}

// ---------------- K2: fused conv1a+BN1+ReLU+conv1b + seg-max(pool1) ----------------
// block = 64 points, 256 threads; thread t owns output channel t for all 64 points
__global__ void __launch_bounds__(256) k_stage1(const float* __restrict__ x,
                                                const float* __restrict__ W1b,
                                                const float* __restrict__ b1b,
                                                int N, int B) {
    __shared__ float xs[3 * 64];
    __shared__ float hs[128 * 64];
    __shared__ int s_segA, s_bnd;
    int tid = threadIdx.x;
    int n0 = blockIdx.x * 64;
    if (tid < 192) xs[tid] = x[(tid >> 6) * N + n0 + (tid & 63)];
    if (tid == 0) {
        int s = 0;
        while (s + 1 < B && g_off[s + 1] <= n0) s++;
        s_segA = s; s_bnd = g_off[s + 1];
    }
    __syncthreads();
    // phase 1: h[128][64] = relu(Wf1 * x + bf1)
    #pragma unroll
    for (int i = 0; i < 32; i++) {
        int e = tid + i * 256;
        int c = e >> 6, p = e & 63;
        float h = g_bf1[c] + g_Wf1[c * 3] * xs[p]
                + g_Wf1[c * 3 + 1] * xs[64 + p]
                + g_Wf1[c * 3 + 2] * xs[128 + p];
        hs[e] = fmaxf(h, 0.f);
    }
    __syncthreads();
    // phase 2: mlp_feat[c][n0..n0+63] = W1b[c][:] . h[:][p]
    float acc[64];
    #pragma unroll
    for (int p = 0; p < 64; p++) acc[p] = 0.f;
    const float* wrow = W1b + tid * 128;
    for (int k0 = 0; k0 < 128; k0 += 16) {
        float4 w4[4];
        w4[0] = *(const float4*)(wrow + k0);
        w4[1] = *(const float4*)(wrow + k0 + 4);
        w4[2] = *(const float4*)(wrow + k0 + 8);
        w4[3] = *(const float4*)(wrow + k0 + 12);
        const float* wv = (const float*)w4;
        #pragma unroll
        for (int kk = 0; kk < 16; kk++) {
            float w = wv[kk];
            const float4* hp = (const float4*)&hs[(k0 + kk) * 64];
            #pragma unroll
            for (int p4 = 0; p4 < 16; p4++) {
                float4 hv = hp[p4];
                acc[p4 * 4 + 0] += w * hv.x;
                acc[p4 * 4 + 1] += w * hv.y;
                acc[p4 * 4 + 2] += w * hv.z;
                acc[p4 * 4 + 3] += w * hv.w;
            }
        }
    }
    float bb = b1b[tid];
    float mA = -CUDART_INF_F, mB = -CUDART_INF_F;
    int bnd = s_bnd;
    float* dst = &g_mlp[tid * N + n0];
    #pragma unroll
    for (int p = 0; p < 64; p++) {
        float v = acc[p] + bb;
        acc[p] = v;
        if (n0 + p < bnd) mA = fmaxf(mA, v); else mB = fmaxf(mB, v);
    }
    #pragma unroll
    for (int p4 = 0; p4 < 16; p4++) {
        *(float4*)(dst + p4 * 4) =
            make_float4(acc[p4 * 4], acc[p4 * 4 + 1], acc[p4 * 4 + 2], acc[p4 * 4 + 3]);
    }
    atomicMax(&g_pool1u[s_segA * 256 + tid], fkey(mA));
    if (bnd < n0 + 64) atomicMax(&g_pool1u[(s_segA + 1) * 256 + tid], fkey(mB));
}

__global__ void k_decode1(int B) {
    int i = blockIdx.x * blockDim.x + threadIdx.x;
    if (i < B * 256) g_pool1[i] = funkey(g_pool1u[i]);
}

// ---------------- K3: y2 = W2a * [mlp_feat; sym] + b2a  (+ BN2 stat partials) ----------------
// classic 128x128x8 SGEMM, 256 threads, 8x8 micro-tile
__global__ void __launch_bounds__(256) k_gemm1(const float* __restrict__ W2a,
                                               const float* __restrict__ b2a,
                                               int N, int B) {
    __shared__ float As[8][132];
    __shared__ float Bs[8][132];
    __shared__ float red[128][17];
    __shared__ int s_seg, s_bnd;
    int tid = threadIdx.x;
    int n0 = blockIdx.x * 128;
    int c0 = blockIdx.y * 128;
    if (tid == 0) {
        int s = 0;
        while (s + 1 < B && g_off[s + 1] <= n0) s++;
        s_seg = s; s_bnd = g_off[s + 1];
    }
    __syncthreads();
    int ty = tid >> 4, tx = tid & 15;
    float accv[8][8];
    #pragma unroll
    for (int i = 0; i < 8; i++)
        #pragma unroll
        for (int j = 0; j < 8; j++) accv[i][j] = 0.f;
    int arow = tid >> 1, acol = (tid & 1) * 4;
    int brow = tid >> 5, bcol = (tid & 31) * 4;
    for (int k0 = 0; k0 < 512; k0 += 8) {
        float4 av = *(const float4*)&W2a[(c0 + arow) * 512 + k0 + acol];
        As[acol + 0][arow] = av.x; As[acol + 1][arow] = av.y;
        As[acol + 2][arow] = av.z; As[acol + 3][arow] = av.w;
        int k = k0 + brow;
        float4 bv;
        if (k < 256) {
            bv = *(const float4*)&g_mlp[k * N + n0 + bcol];
        } else {
            int cs = k - 256;
            float t[4];
            #pragma unroll
            for (int ii = 0; ii < 4; ii++) {
                int n = n0 + bcol + ii;
                int sg = (n < s_bnd) ? s_seg : s_seg + 1;
                t[ii] = g_pool1[sg * 256 + cs];
            }
            bv = make_float4(t[0], t[1], t[2], t[3]);
        }
        *(float4*)&Bs[brow][bcol] = bv;
        __syncthreads();
        #pragma unroll
        for (int kk = 0; kk < 8; kk++) {
            float a[8], bR[8];
            *(float4*)(a)      = *(const float4*)&As[kk][ty * 8];
            *(float4*)(a + 4)  = *(const float4*)&As[kk][ty * 8 + 4];
            *(float4*)(bR)     = *(const float4*)&Bs[kk][tx * 8];
            *(float4*)(bR + 4) = *(const float4*)&Bs[kk][tx * 8 + 4];
            #pragma unroll
            for (int i = 0; i < 8; i++)
                #pragma unroll
                for (int j = 0; j < 8; j++) accv[i][j] += a[i] * bR[j];
        }
        __syncthreads();
    }
    // epilogue: write y2, accumulate sum/sumsq partials per channel (deterministic)
    int nb = blockIdx.x;
    float rs[8], rq[8];
    #pragma unroll
    for (int i = 0; i < 8; i++) {
        int c = c0 + ty * 8 + i;
        float bias = b2a[c];
        float s = 0.f, q = 0.f;
        float vbuf[8];
        #pragma unroll
        for (int j = 0; j < 8; j++) {
            float v = accv[i][j] + bias;
            vbuf[j] = v; s += v; q += v * v;
        }
        float* dst = &g_y2v[c * N + n0 + tx * 8];
        *(float4*)(dst)     = make_float4(vbuf[0], vbuf[1], vbuf[2], vbuf[3]);
        *(float4*)(dst + 4) = make_float4(vbuf[4], vbuf[5], vbuf[6], vbuf[7]);
        rs[i] = s; rq[i] = q;
    }
    #pragma unroll
    for (int i = 0; i < 8; i++) red[ty * 8 + i][tx] = rs[i];
    __syncthreads();
    if (tid < 128) {
        float s = 0.f;
        #pragma unroll
        for (int t = 0; t < 16; t++) s += red[tid][t];
        g_psum[(c0 + tid) * 1024 + nb] = s;
    }
    __syncthreads();
    #pragma unroll
    for (int i = 0; i < 8; i++) red[ty * 8 + i][tx] = rq[i];
    __syncthreads();
    if (tid < 128) {
        float q = 0.f;
        #pragma unroll
        for (int t = 0; t < 16; t++) q += red[tid][t];
        g_psq[(c0 + tid) * 1024 + nb] = q;
    }
}

// ---------------- K4: reduce BN2 stats, fold into scale/shift ----------------
__global__ void k_bn2(const float* __restrict__ g2, const float* __restrict__ be2,
                      int N, int NB) {
    int c = blockIdx.x * blockDim.x + threadIdx.x;
    if (c >= 512) return;
    double s = 0, q = 0;
    for (int nb = 0; nb < NB; nb++) { s += (double)g_psum[c * 1024 + nb]; q += (double)g_psq[c * 1024 + nb]; }
    double mean = s / (double)N;
    double var  = q / (double)N - mean * mean;
    float a = g2[c] * rsqrtf((float)var + EPSV);
    g_a2[c] = a;
    g_c2[c] = be2[c] - (float)mean * a;
}

// ---------------- K5: comb = W2b * relu(a2*y2+c2) + b2b, fused seg-max ----------------
__global__ void __launch_bounds__(256) k_gemm2(const float* __restrict__ W2b,
                                               const float* __restrict__ b2b,
                                               int N, int B) {
    __shared__ float As[8][132];
    __shared__ float Bs[8][132];
    __shared__ float red[128][17];
    __shared__ int s_seg, s_bnd;
    int tid = threadIdx.x;
    int n0 = blockIdx.x * 128;
    int c0 = blockIdx.y * 128;
    if (tid == 0) {
        int s = 0;
        while (s + 1 < B && g_off[s + 1] <= n0) s++;
        s_seg = s; s_bnd = g_off[s + 1];
    }
    __syncthreads();
    int ty = tid >> 4, tx = tid & 15;
    float accv[8][8];
    #pragma unroll
    for (int i = 0; i < 8; i++)
        #pragma unroll
        for (int j = 0; j < 8; j++) accv[i][j] = 0.f;
    int arow = tid >> 1, acol = (tid & 1) * 4;
    int brow = tid >> 5, bcol = (tid & 31) * 4;
    for (int k0 = 0; k0 < 512; k0 += 8) {
        float4 av = *(const float4*)&W2b[(c0 + arow) * 512 + k0 + acol];
        As[acol + 0][arow] = av.x; As[acol + 1][arow] = av.y;
        As[acol + 2][arow] = av.z; As[acol + 3][arow] = av.w;
        int k = k0 + brow;
        float4 yv = *(const float4*)&g_y2v[k * N + n0 + bcol];
        float a = g_a2[k], cc = g_c2[k];
        float4 bv;
        bv.x = fmaxf(yv.x * a + cc, 0.f);
        bv.y = fmaxf(yv.y * a + cc, 0.f);
        bv.z = fmaxf(yv.z * a + cc, 0.f);
        bv.w = fmaxf(yv.w * a + cc, 0.f);
        *(float4*)&Bs[brow][bcol] = bv;
        __syncthreads();
        #pragma unroll
        for (int kk = 0; kk < 8; kk++) {
            float a8[8], bR[8];
            *(float4*)(a8)      = *(const float4*)&As[kk][ty * 8];
            *(float4*)(a8 + 4)  = *(const float4*)&As[kk][ty * 8 + 4];
            *(float4*)(bR)      = *(const float4*)&Bs[kk][tx * 8];
            *(float4*)(bR + 4)  = *(const float4*)&Bs[kk][tx * 8 + 4];
            #pragma unroll
            for (int i = 0; i < 8; i++)
                #pragma unroll
                for (int j = 0; j < 8; j++) accv[i][j] += a8[i] * bR[j];
        }
        __syncthreads();
    }
    // epilogue: segment max over the 128-point tile (<= 2 segments)
    bool hasB = (s_bnd < n0 + 128);
    float mA[8], mB[8];
    #pragma unroll
    for (int i = 0; i < 8; i++) {
        int c = c0 + ty * 8 + i;
        float bias = b2b[c];
        float a_ = -CUDART_INF_F, b_ = -CUDART_INF_F;
        #pragma unroll
        for (int j = 0; j < 8; j++) {
            float v = accv[i][j] + bias;
            int n = n0 + tx * 8 + j;
            if (n < s_bnd) a_ = fmaxf(a_, v); else b_ = fmaxf(b_, v);
        }
        mA[i] = a_; mB[i] = b_;
    }
    #pragma unroll
    for (int i = 0; i < 8; i++) red[ty * 8 + i][tx] = mA[i];
    __syncthreads();
    if (tid < 128) {
        float m = -CUDART_INF_F;
        #pragma unroll
        for (int t = 0; t < 16; t++) m = fmaxf(m, red[tid][t]);
        atomicMax(&g_pool2u[s_seg * 1024 + c0 + tid], fkey(m));
    }
    __syncthreads();
    if (hasB) {
        #pragma unroll
        for (int i = 0; i < 8; i++) red[ty * 8 + i][tx] = mB[i];
        __syncthreads();
        if (tid < 128) {
            float m = -CUDART_INF_F;
            #pragma unroll
            for (int t = 0; t < 16; t++) m = fmaxf(m, red[tid][t]);
            atomicMax(&g_pool2u[(s_seg + 1) * 1024 + c0 + tid], fkey(m));
        }
    }
}

// ---------------- K6: decode output ----------------
__global__ void k_out(float* __restrict__ out, int B) {
    int i = blockIdx.x * blockDim.x + threadIdx.x;
    if (i < B * 1024) out[i] = funkey(g_pool2u[i]);
}

// ---------------- launch ----------------
extern "C" void kernel_launch(void* const* d_in, const int* in_sizes, int n_in,
                              void* d_out, int out_size) {
    const float* x   = (const float*)d_in[0];
    const int*   np  = (const int*)  d_in[1];
    const float* W1a = (const float*)d_in[2];
    const float* b1a = (const float*)d_in[3];
    const float* g1  = (const float*)d_in[4];
    const float* be1 = (const float*)d_in[5];
    const float* W1b = (const float*)d_in[6];
    const float* b1b = (const float*)d_in[7];
    const float* W2a = (const float*)d_in[8];
    const float* b2a = (const float*)d_in[9];
    const float* g2  = (const float*)d_in[10];
    const float* be2 = (const float*)d_in[11];
    const float* W2b = (const float*)d_in[12];
    const float* b2b = (const float*)d_in[13];
    int N = in_sizes[0] / 3;
    int B = in_sizes[1];
    if (N > MAXN) N = MAXN;

    k_init<<<32, 256>>>(np, B);
    k_xstats<<<128, 256>>>(x, N);
    k_fold1<<<1, 128>>>(W1a, b1a, g1, be1, N, 128);
    k_stage1<<<N / 64, 256>>>(x, W1b, b1b, N, B);
    k_decode1<<<(B * 256 + 255) / 256, 256>>>(B);
    dim3 g3(N / 128, 4);
    k_gemm1<<<g3, 256>>>(W2a, b2a, N, B);
    k_bn2<<<2, 256>>>(g2, be2, N, N / 128);
    dim3 g5(N / 128, 8);
    k_gemm2<<<g5, 256>>>(W2b, b2b, N, B);
    k_out<<<(B * 1024 + 255) / 256, 256>>>((float*)d_out, B);
}

// round 4
// speedup vs baseline: 2.6676x; 2.6676x over previous
#include <cuda_runtime.h>
#include <cuda_fp16.h>
#include <math_constants.h>

#define MAXN 131072
#define MAXB 32
#define EPSV 1e-5f

// ---------------- scratch (static device globals; no allocation) ----------------
__device__ __align__(16) __half g_mlph[256 * MAXN];   // mlp_feat fp16 [256][N] (64 MB)
__device__ __align__(16) __half g_y2h [512 * MAXN];   // pre-BN2 y2 fp16 [512][N] (128 MB)
__device__ __align__(16) __half g_W2a_h[512 * 512];
__device__ __align__(16) __half g_W2b_h[1024 * 512];
__device__ float    g_psum[512 * 1024];   // per-(c, n-block) partial sums
__device__ float    g_psq [512 * 1024];
__device__ float    g_xpart[128 * 9];
__device__ float    g_Wf1[128 * 3];
__device__ float    g_bf1[128];
__device__ float    g_a2[512];
__device__ float    g_c2[512];
__device__ unsigned g_pool1u[MAXB * 256];
__device__ __half   g_pool1h[MAXB * 256];
__device__ unsigned g_pool2u[MAXB * 1024];
__device__ int      g_off[MAXB + 1];
__device__ unsigned char g_segid[MAXN];

// monotonic float<->uint key for exact atomic max
__device__ __forceinline__ unsigned fkey(float f) {
    unsigned u = __float_as_uint(f);
    return (u & 0x80000000u) ? ~u : (u | 0x80000000u);
}
__device__ __forceinline__ float funkey(unsigned k) {
    return (k & 0x80000000u) ? __uint_as_float(k & 0x7fffffffu)
                             : __uint_as_float(~k);
}

__device__ __forceinline__ unsigned smem_u32(const void* p) {
    return (unsigned)__cvta_generic_to_shared(p);
}
__device__ __forceinline__ void ldsm_x4(unsigned* r, unsigned addr) {
    asm volatile("ldmatrix.sync.aligned.m8n8.x4.shared.b16 {%0,%1,%2,%3},[%4];"
                 : "=r"(r[0]), "=r"(r[1]), "=r"(r[2]), "=r"(r[3]) : "r"(addr));
}
__device__ __forceinline__ void ldsm_x4_t(unsigned* r, unsigned addr) {
    asm volatile("ldmatrix.sync.aligned.m8n8.x4.trans.shared.b16 {%0,%1,%2,%3},[%4];"
                 : "=r"(r[0]), "=r"(r[1]), "=r"(r[2]), "=r"(r[3]) : "r"(addr));
}
__device__ __forceinline__ void mma16816(float* d, const unsigned* a, unsigned b0, unsigned b1) {
    asm volatile("mma.sync.aligned.m16n8k16.row.col.f32.f16.f16.f32 "
                 "{%0,%1,%2,%3},{%4,%5,%6,%7},{%8,%9},{%0,%1,%2,%3};"
                 : "+f"(d[0]), "+f"(d[1]), "+f"(d[2]), "+f"(d[3])
                 : "r"(a[0]), "r"(a[1]), "r"(a[2]), "r"(a[3]), "r"(b0), "r"(b1));
}

// ---------------- K0: offsets + pool init ----------------
__global__ void k_init(const int* npts, int B) {
    int tid = blockIdx.x * blockDim.x + threadIdx.x;
    if (blockIdx.x == 0 && threadIdx.x == 0) {
        int acc = 0; g_off[0] = 0;
        for (int b = 0; b < B; b++) { acc += npts[b]; g_off[b + 1] = acc; }
    }
    int stride = gridDim.x * blockDim.x;
    for (int i = tid; i < MAXB * 256;  i += stride) g_pool1u[i] = 0u;
    for (int i = tid; i < MAXB * 1024; i += stride) g_pool2u[i] = 0u;
}

__global__ void k_segid(int N, int B) {
    int n = blockIdx.x * blockDim.x + threadIdx.x;
    if (n >= N) return;
    int s = 0;
    while (s + 1 < B && g_off[s + 1] <= n) s++;
    g_segid[n] = (unsigned char)s;
}

__global__ void k_convW(const float* __restrict__ W2a, const float* __restrict__ W2b) {
    int i = blockIdx.x * blockDim.x + threadIdx.x;
    if (i < 512 * 512)  g_W2a_h[i] = __float2half_rn(W2a[i]);
    if (i < 1024 * 512) g_W2b_h[i] = __float2half_rn(W2b[i]);
}

// ---------------- K1a: x moments ----------------
__global__ void k_xstats(const float* __restrict__ x, int N) {
    float s0 = 0, s1 = 0, s2 = 0, q0 = 0, q1 = 0, q2 = 0, q3 = 0, q4 = 0, q5 = 0;
    int stride = gridDim.x * blockDim.x;
    for (int n = blockIdx.x * blockDim.x + threadIdx.x; n < N; n += stride) {
        float a = x[n], b = x[N + n], c = x[2 * N + n];
        s0 += a; s1 += b; s2 += c;
        q0 += a * a; q1 += a * b; q2 += a * c; q3 += b * b; q4 += b * c; q5 += c * c;
    }
    __shared__ float rb[256];
    float vals[9] = {s0, s1, s2, q0, q1, q2, q3, q4, q5};
    for (int v = 0; v < 9; v++) {
        rb[threadIdx.x] = vals[v];
        __syncthreads();
        for (int st = 128; st > 0; st >>= 1) {
            if (threadIdx.x < st) rb[threadIdx.x] += rb[threadIdx.x + st];
            __syncthreads();
        }
        if (threadIdx.x == 0) g_xpart[blockIdx.x * 9 + v] = rb[0];
        __syncthreads();
    }
}

// ---------------- K1b: fold BN1 into conv1a ----------------
__global__ void k_fold1(const float* __restrict__ W1a, const float* __restrict__ b1a,
                        const float* __restrict__ g1,  const float* __restrict__ be1,
                        int N, int nblocks) {
    __shared__ double S[9];
    __shared__ float mu[3], C[3][3];
    if (threadIdx.x < 9) {
        double a = 0;
        for (int b = 0; b < nblocks; b++) a += (double)g_xpart[b * 9 + threadIdx.x];
        S[threadIdx.x] = a;
    }
    __syncthreads();
    if (threadIdx.x == 0) {
        double invN = 1.0 / (double)N;
        double m0 = S[0] * invN, m1 = S[1] * invN, m2 = S[2] * invN;
        mu[0] = (float)m0; mu[1] = (float)m1; mu[2] = (float)m2;
        C[0][0] = (float)(S[3] * invN - m0 * m0);
        C[0][1] = (float)(S[4] * invN - m0 * m1);
        C[0][2] = (float)(S[5] * invN - m0 * m2);
        C[1][1] = (float)(S[6] * invN - m1 * m1);
        C[1][2] = (float)(S[7] * invN - m1 * m2);
        C[2][2] = (float)(S[8] * invN - m2 * m2);
        C[1][0] = C[0][1]; C[2][0] = C[0][2]; C[2][1] = C[1][2];
    }
    __syncthreads();
    int c = threadIdx.x;
    float w0 = W1a[c * 3], w1 = W1a[c * 3 + 1], w2 = W1a[c * 3 + 2];
    float mean1 = w0 * mu[0] + w1 * mu[1] + w2 * mu[2] + b1a[c];
    float var1 = w0 * w0 * C[0][0] + w1 * w1 * C[1][1] + w2 * w2 * C[2][2]
               + 2.f * (w0 * w1 * C[0][1] + w0 * w2 * C[0][2] + w1 * w2 * C[1][2]);
    float a = g1[c] * rsqrtf(var1 + EPSV);
    g_Wf1[c * 3 + 0] = a * w0;
    g_Wf1[c * 3 + 1] = a * w1;
    g_Wf1[c * 3 + 2] = a * w2;
    g_bf1[c] = a * (b1a[c] - mean1) + be1[c];
}

// ---------------- K2: fused conv1a+BN1+ReLU+conv1b + seg-max(pool1) ----------------
__global__ void __launch_bounds__(256) k_stage1(const float* __restrict__ x,
                                                const float* __restrict__ W1b,
                                                const float* __restrict__ b1b,
                                                int N, int B) {
    __shared__ float xs[3 * 64];
    __shared__ float hs[128 * 64];
    __shared__ int s_segA, s_bnd;
    int tid = threadIdx.x;
    int n0 = blockIdx.x * 64;
    if (tid < 192) xs[tid] = x[(tid >> 6) * N + n0 + (tid & 63)];
    if (tid == 0) {
        int s = 0;
        while (s + 1 < B && g_off[s + 1] <= n0) s++;
        s_segA = s; s_bnd = g_off[s + 1];
    }
    __syncthreads();
    #pragma unroll
    for (int i = 0; i < 32; i++) {
        int e = tid + i * 256;
        int c = e >> 6, p = e & 63;
        float h = g_bf1[c] + g_Wf1[c * 3] * xs[p]
                + g_Wf1[c * 3 + 1] * xs[64 + p]
                + g_Wf1[c * 3 + 2] * xs[128 + p];
        hs[e] = fmaxf(h, 0.f);
    }
    __syncthreads();
    float acc[64];
    #pragma unroll
    for (int p = 0; p < 64; p++) acc[p] = 0.f;
    const float* wrow = W1b + tid * 128;
    for (int k0 = 0; k0 < 128; k0 += 16) {
        float4 w4[4];
        w4[0] = *(const float4*)(wrow + k0);
        w4[1] = *(const float4*)(wrow + k0 + 4);
        w4[2] = *(const float4*)(wrow + k0 + 8);
        w4[3] = *(const float4*)(wrow + k0 + 12);
        const float* wv = (const float*)w4;
        #pragma unroll
        for (int kk = 0; kk < 16; kk++) {
            float w = wv[kk];
            const float4* hp = (const float4*)&hs[(k0 + kk) * 64];
            #pragma unroll
            for (int p4 = 0; p4 < 16; p4++) {
                float4 hv = hp[p4];
                acc[p4 * 4 + 0] += w * hv.x;
                acc[p4 * 4 + 1] += w * hv.y;
                acc[p4 * 4 + 2] += w * hv.z;
                acc[p4 * 4 + 3] += w * hv.w;
            }
        }
    }
    float bb = b1b[tid];
    float mA = -CUDART_INF_F, mB = -CUDART_INF_F;
    int bnd = s_bnd;
    __half* dst = &g_mlph[(size_t)tid * N + n0];
    #pragma unroll
    for (int p = 0; p < 64; p++) {
        float v = acc[p] + bb;
        acc[p] = v;
        if (n0 + p < bnd) mA = fmaxf(mA, v); else mB = fmaxf(mB, v);
    }
    #pragma unroll
    for (int p2 = 0; p2 < 32; p2++) {
        *(__half2*)&dst[p2 * 2] = __floats2half2_rn(acc[2 * p2], acc[2 * p2 + 1]);
    }
    atomicMax(&g_pool1u[s_segA * 256 + tid], fkey(mA));
    if (bnd < n0 + 64) atomicMax(&g_pool1u[(s_segA + 1) * 256 + tid], fkey(mB));
}

__global__ void k_decode1(int B) {
    int i = blockIdx.x * blockDim.x + threadIdx.x;
    if (i < B * 256) g_pool1h[i] = __float2half_rn(funkey(g_pool1u[i]));
}

// ---------------- tensor-core GEMMs ----------------
// MODE 0: y2 = W2a * [mlp;sym] + b2a, epilogue: store y2 fp16 + BN2 stat partials
// MODE 1: comb = W2b * relu(a2*y2+c2) + b2b, epilogue: fused segment max
// Tiles: 128 (c) x 256 (n) x 16 (k), 256 threads, warp = 64x64, m16n8k16 fp16 mma.
template<int MODE>
__global__ void __launch_bounds__(256) k_mma(const float* __restrict__ bias,
                                             int N, int B) {
    __shared__ __align__(16) __half As[2][128][24];
    __shared__ __align__(16) __half Bs[2][16][264];
    __shared__ float s_red[128][4];

    const int tid = threadIdx.x, lane = tid & 31, wid = tid >> 5;
    const int wm = wid & 1, wn = wid >> 1;
    const int quad = lane >> 2, qlane = lane & 3;
    const int n0 = blockIdx.x * 256;
    const int c0 = blockIdx.y * 128;

    const __half* __restrict__ Aw = (MODE == 0 ? g_W2a_h : g_W2b_h);
    const __half* AglobBase = Aw + (size_t)(c0 + (tid >> 1)) * 512 + (tid & 1) * 8;
    const int kloc = tid >> 4;
    const int ncol = n0 + (tid & 15) * 16;

    // smem addresses for ldmatrix (both buffers)
    unsigned aAddr[2][4], bAddr[2][4];
    #pragma unroll
    for (int s = 0; s < 2; s++) {
        unsigned aBase = smem_u32(&As[s][0][0]);
        unsigned bBase = smem_u32(&Bs[s][0][0]);
        #pragma unroll
        for (int mf = 0; mf < 4; mf++)
            aAddr[s][mf] = aBase + (((wm * 64 + mf * 16 + (lane & 15)) * 24
                                     + (lane >> 4) * 8) << 1);
        #pragma unroll
        for (int np = 0; np < 4; np++)
            bAddr[s][np] = bBase + (((lane & 15) * 264 + wn * 64 + np * 16
                                     + (lane >> 4) * 8) << 1);
    }

    float acc[4][8][4];
    #pragma unroll
    for (int m = 0; m < 4; m++)
        #pragma unroll
        for (int n = 0; n < 8; n++)
            #pragma unroll
            for (int v = 0; v < 4; v++) acc[m][n][v] = 0.f;

    // prefetch helpers
    uint4 pa, pb0, pb1;
    auto loadTiles = [&](int ks) {
        pa = *(const uint4*)(AglobBase + ks * 16);
        int krow = ks * 16 + kloc;
        if (MODE == 0) {
            if (krow < 256) {
                const uint4* p = (const uint4*)(g_mlph + (size_t)krow * N + ncol);
                pb0 = p[0]; pb1 = p[1];
            } else {
                union { __half h[16]; uint4 u[2]; } tb;
                const unsigned char* sp = g_segid + ncol;
                int cs = krow - 256;
                #pragma unroll
                for (int j = 0; j < 16; j++) tb.h[j] = g_pool1h[sp[j] * 256 + cs];
                pb0 = tb.u[0]; pb1 = tb.u[1];
            }
        } else {
            const uint4* p = (const uint4*)(g_y2h + (size_t)krow * N + ncol);
            union { __half h[16]; uint4 u[2]; } src, tb;
            src.u[0] = p[0]; src.u[1] = p[1];
            float a = g_a2[krow], cc = g_c2[krow];
            #pragma unroll
            for (int j = 0; j < 16; j++)
                tb.h[j] = __float2half_rn(fmaxf(__half2float(src.h[j]) * a + cc, 0.f));
            pb0 = tb.u[0]; pb1 = tb.u[1];
        }
    };
    auto storeTiles = [&](int s) {
        *(uint4*)&As[s][tid >> 1][(tid & 1) * 8] = pa;
        *(uint4*)&Bs[s][kloc][(tid & 15) * 16] = pb0;
        *(uint4*)&Bs[s][kloc][(tid & 15) * 16 + 8] = pb1;
    };

    loadTiles(0);
    storeTiles(0);
    __syncthreads();

    for (int ks = 0; ks < 32; ks++) {
        int cur = ks & 1;
        if (ks < 31) loadTiles(ks + 1);
        unsigned af[4][4], bf[4][4];
        #pragma unroll
        for (int mf = 0; mf < 4; mf++) ldsm_x4(af[mf], aAddr[cur][mf]);
        #pragma unroll
        for (int np = 0; np < 4; np++) ldsm_x4_t(bf[np], bAddr[cur][np]);
        #pragma unroll
        for (int mf = 0; mf < 4; mf++)
            #pragma unroll
            for (int nf = 0; nf < 8; nf++)
                mma16816(acc[mf][nf], af[mf], bf[nf >> 1][(nf & 1) * 2],
                         bf[nf >> 1][(nf & 1) * 2 + 1]);
        if (ks < 31) storeTiles(cur ^ 1);
        __syncthreads();
    }

    // ---------------- epilogues ----------------
    if (MODE == 0) {
        int nb = blockIdx.x;
        float sums[4][2], sqs[4][2];
        #pragma unroll
        for (int mf = 0; mf < 4; mf++) {
            int cA = c0 + wm * 64 + mf * 16 + quad;
            int cB = cA + 8;
            float bA = bias[cA], bB = bias[cB];
            float sA = 0, qA = 0, sB = 0, qB = 0;
            #pragma unroll
            for (int nf = 0; nf < 8; nf++) {
                int n = n0 + wn * 64 + nf * 8 + qlane * 2;
                float v0 = acc[mf][nf][0] + bA;
                float v1 = acc[mf][nf][1] + bA;
                float v2 = acc[mf][nf][2] + bB;
                float v3 = acc[mf][nf][3] + bB;
                *(__half2*)&g_y2h[(size_t)cA * N + n] = __floats2half2_rn(v0, v1);
                *(__half2*)&g_y2h[(size_t)cB * N + n] = __floats2half2_rn(v2, v3);
                sA += v0 + v1; qA += v0 * v0 + v1 * v1;
                sB += v2 + v3; qB += v2 * v2 + v3 * v3;
            }
            sums[mf][0] = sA; sums[mf][1] = sB;
            sqs[mf][0] = qA;  sqs[mf][1] = qB;
        }
        #pragma unroll
        for (int mf = 0; mf < 4; mf++)
            #pragma unroll
            for (int h = 0; h < 2; h++) {
                float v = sums[mf][h];
                v += __shfl_xor_sync(0xffffffff, v, 1);
                v += __shfl_xor_sync(0xffffffff, v, 2);
                if (qlane == 0) s_red[wm * 64 + mf * 16 + h * 8 + quad][wn] = v;
            }
        __syncthreads();
        if (tid < 128)
            g_psum[(size_t)(c0 + tid) * 512 + nb] =
                s_red[tid][0] + s_red[tid][1] + s_red[tid][2] + s_red[tid][3];
        __syncthreads();
        #pragma unroll
        for (int mf = 0; mf < 4; mf++)
            #pragma unroll
            for (int h = 0; h < 2; h++) {
                float v = sqs[mf][h];
                v += __shfl_xor_sync(0xffffffff, v, 1);
                v += __shfl_xor_sync(0xffffffff, v, 2);
                if (qlane == 0) s_red[wm * 64 + mf * 16 + h * 8 + quad][wn] = v;
            }
        __syncthreads();
        if (tid < 128)
            g_psq[(size_t)(c0 + tid) * 512 + nb] =
                s_red[tid][0] + s_red[tid][1] + s_red[tid][2] + s_red[tid][3];
    } else {
        __shared__ int s_seg, s_bnd;
        if (tid == 0) {
            int s = g_segid[n0];
            s_seg = s; s_bnd = g_off[s + 1];
        }
        __syncthreads();
        int bnd = s_bnd;
        bool hasB = (bnd < n0 + 256);
        float mA[4][2], mB[4][2];
        #pragma unroll
        for (int mf = 0; mf < 4; mf++) {
            int cA = c0 + wm * 64 + mf * 16 + quad;
            float bA = bias[cA], bB = bias[cA + 8];
            float a0 = -CUDART_INF_F, b0 = -CUDART_INF_F;
            float a1 = -CUDART_INF_F, b1 = -CUDART_INF_F;
            #pragma unroll
            for (int nf = 0; nf < 8; nf++) {
                int n = n0 + wn * 64 + nf * 8 + qlane * 2;
                float v0 = acc[mf][nf][0] + bA;
                float v1 = acc[mf][nf][1] + bA;
                float v2 = acc[mf][nf][2] + bB;
                float v3 = acc[mf][nf][3] + bB;
                if (n < bnd)     a0 = fmaxf(a0, v0); else b0 = fmaxf(b0, v0);
                if (n + 1 < bnd) a0 = fmaxf(a0, v1); else b0 = fmaxf(b0, v1);
                if (n < bnd)     a1 = fmaxf(a1, v2); else b1 = fmaxf(b1, v2);
                if (n + 1 < bnd) a1 = fmaxf(a1, v3); else b1 = fmaxf(b1, v3);
            }
            mA[mf][0] = a0; mA[mf][1] = a1;
            mB[mf][0] = b0; mB[mf][1] = b1;
        }
        #pragma unroll
        for (int mf = 0; mf < 4; mf++)
            #pragma unroll
            for (int h = 0; h < 2; h++) {
                float v = mA[mf][h];
                v = fmaxf(v, __shfl_xor_sync(0xffffffff, v, 1));
                v = fmaxf(v, __shfl_xor_sync(0xffffffff, v, 2));
                if (qlane == 0) s_red[wm * 64 + mf * 16 + h * 8 + quad][wn] = v;
            }
        __syncthreads();
        if (tid < 128) {
            float m = fmaxf(fmaxf(s_red[tid][0], s_red[tid][1]),
                            fmaxf(s_red[tid][2], s_red[tid][3]));
            atomicMax(&g_pool2u[s_seg * 1024 + c0 + tid], fkey(m));
        }
        __syncthreads();
        if (hasB) {
            #pragma unroll
            for (int mf = 0; mf < 4; mf++)
                #pragma unroll
                for (int h = 0; h < 2; h++) {
                    float v = mB[mf][h];
                    v = fmaxf(v, __shfl_xor_sync(0xffffffff, v, 1));
                    v = fmaxf(v, __shfl_xor_sync(0xffffffff, v, 2));
                    if (qlane == 0) s_red[wm * 64 + mf * 16 + h * 8 + quad][wn] = v;
                }
            __syncthreads();
            if (tid < 128) {
                float m = fmaxf(fmaxf(s_red[tid][0], s_red[tid][1]),
                                fmaxf(s_red[tid][2], s_red[tid][3]));
                atomicMax(&g_pool2u[(s_seg + 1) * 1024 + c0 + tid], fkey(m));
            }
        }
    }
}

// ---------------- K4: reduce BN2 stats ----------------
__global__ void k_bn2(const float* __restrict__ g2, const float* __restrict__ be2,
                      int N, int NB) {
    int c = blockIdx.x * blockDim.x + threadIdx.x;
    if (c >= 512) return;
    double s = 0, q = 0;
    for (int nb = 0; nb < NB; nb++) {
        s += (double)g_psum[(size_t)c * 512 + nb];
        q += (double)g_psq[(size_t)c * 512 + nb];
    }
    double mean = s / (double)N;
    double var  = q / (double)N - mean * mean;
    float a = g2[c] * rsqrtf((float)var + EPSV);
    g_a2[c] = a;
    g_c2[c] = be2[c] - (float)mean * a;
}

// ---------------- K6: decode output ----------------
__global__ void k_out(float* __restrict__ out, int B) {
    int i = blockIdx.x * blockDim.x + threadIdx.x;
    if (i < B * 1024) out[i] = funkey(g_pool2u[i]);
}

// ---------------- launch ----------------
extern "C" void kernel_launch(void* const* d_in, const int* in_sizes, int n_in,
                              void* d_out, int out_size) {
    const float* x   = (const float*)d_in[0];
    const int*   np  = (const int*)  d_in[1];
    const float* W1a = (const float*)d_in[2];
    const float* b1a = (const float*)d_in[3];
    const float* g1  = (const float*)d_in[4];
    const float* be1 = (const float*)d_in[5];
    const float* W1b = (const float*)d_in[6];
    const float* b1b = (const float*)d_in[7];
    const float* W2a = (const float*)d_in[8];
    const float* b2a = (const float*)d_in[9];
    const float* g2  = (const float*)d_in[10];
    const float* be2 = (const float*)d_in[11];
    const float* W2b = (const float*)d_in[12];
    const float* b2b = (const float*)d_in[13];
    int N = in_sizes[0] / 3;
    int B = in_sizes[1];
    if (N > MAXN) N = MAXN;

    k_init<<<32, 256>>>(np, B);
    k_segid<<<(N + 255) / 256, 256>>>(N, B);
    k_convW<<<2048, 256>>>(W2a, W2b);
    k_xstats<<<128, 256>>>(x, N);
    k_fold1<<<1, 128>>>(W1a, b1a, g1, be1, N, 128);
    k_stage1<<<N / 64, 256>>>(x, W1b, b1b, N, B);
    k_decode1<<<(B * 256 + 255) / 256, 256>>>(B);
    dim3 g3(N / 256, 4);
    k_mma<0><<<g3, 256>>>(b2a, N, B);
    k_bn2<<<2, 256>>>(g2, be2, N, N / 256);
    dim3 g5(N / 256, 8);
    k_mma<1><<<g5, 256>>>(b2b, N, B);
    k_out<<<(B * 1024 + 255) / 256, 256>>>((float*)d_out, B);
}

// round 5
// speedup vs baseline: 2.6700x; 1.0009x over previous
#include <cuda_runtime.h>
#include <cuda_fp16.h>
#include <math_constants.h>

#define MAXN 131072
#define MAXB 32
#define EPSV 1e-5f

// ---------------- scratch (static device globals; no allocation) ----------------
__device__ __align__(16) __half g_mlph[256 * MAXN];   // mlp_feat fp16 [256][N] (64 MB)
__device__ __align__(16) __half g_y2h [512 * MAXN];   // pre-BN2 y2 fp16 [512][N] (128 MB)
__device__ __align__(16) __half g_W2a_h[512 * 512];
__device__ __align__(16) __half g_W2b_h[1024 * 512];
__device__ float    g_psum[512 * 1024];   // per-(c, n-block) partial sums
__device__ float    g_psq [512 * 1024];
__device__ float    g_xpart[128 * 9];
__device__ float    g_Wf1[128 * 3];
__device__ float    g_bf1[128];
__device__ float    g_a2[512];
__device__ float    g_c2[512];
__device__ unsigned g_pool1u[MAXB * 256];
__device__ __half   g_pool1h[MAXB * 256];
__device__ unsigned g_pool2u[MAXB * 1024];
__device__ int      g_off[MAXB + 1];
__device__ unsigned char g_segid[MAXN];

// monotonic float<->uint key for exact atomic max
__device__ __forceinline__ unsigned fkey(float f) {
    unsigned u = __float_as_uint(f);
    return (u & 0x80000000u) ? ~u : (u | 0x80000000u);
}
__device__ __forceinline__ float funkey(unsigned k) {
    return (k & 0x80000000u) ? __uint_as_float(k & 0x7fffffffu)
                             : __uint_as_float(~k);
}

__device__ __forceinline__ unsigned smem_u32(const void* p) {
    return (unsigned)__cvta_generic_to_shared(p);
}
__device__ __forceinline__ void ldsm_x4(unsigned* r, unsigned addr) {
    asm volatile("ldmatrix.sync.aligned.m8n8.x4.shared.b16 {%0,%1,%2,%3},[%4];"
                 : "=r"(r[0]), "=r"(r[1]), "=r"(r[2]), "=r"(r[3]) : "r"(addr));
}
__device__ __forceinline__ void ldsm_x4_t(unsigned* r, unsigned addr) {
    asm volatile("ldmatrix.sync.aligned.m8n8.x4.trans.shared.b16 {%0,%1,%2,%3},[%4];"
                 : "=r"(r[0]), "=r"(r[1]), "=r"(r[2]), "=r"(r[3]) : "r"(addr));
}
__device__ __forceinline__ void mma16816(float* d, const unsigned* a, unsigned b0, unsigned b1) {
    asm volatile("mma.sync.aligned.m16n8k16.row.col.f32.f16.f16.f32 "
                 "{%0,%1,%2,%3},{%4,%5,%6,%7},{%8,%9},{%0,%1,%2,%3};"
                 : "+f"(d[0]), "+f"(d[1]), "+f"(d[2]), "+f"(d[3])
                 : "r"(a[0]), "r"(a[1]), "r"(a[2]), "r"(a[3]), "r"(b0), "r"(b1));
}

// ---------------- K0: offsets + pool init ----------------
__global__ void k_init(const int* npts, int B) {
    int tid = blockIdx.x * blockDim.x + threadIdx.x;
    if (blockIdx.x == 0 && threadIdx.x == 0) {
        int acc = 0; g_off[0] = 0;
        for (int b = 0; b < B; b++) { acc += npts[b]; g_off[b + 1] = acc; }
    }
    int stride = gridDim.x * blockDim.x;
    for (int i = tid; i < MAXB * 256;  i += stride) g_pool1u[i] = 0u;
    for (int i = tid; i < MAXB * 1024; i += stride) g_pool2u[i] = 0u;
}

__global__ void k_segid(int N, int B) {
    int n = blockIdx.x * blockDim.x + threadIdx.x;
    if (n >= N) return;
    int s = 0;
    while (s + 1 < B && g_off[s + 1] <= n) s++;
    g_segid[n] = (unsigned char)s;
}

__global__ void k_convW(const float* __restrict__ W2a, const float* __restrict__ W2b) {
    int i = blockIdx.x * blockDim.x + threadIdx.x;
    if (i < 512 * 512)  g_W2a_h[i] = __float2half_rn(W2a[i]);
    if (i < 1024 * 512) g_W2b_h[i] = __float2half_rn(W2b[i]);
}

// ---------------- K1a: x moments ----------------
__global__ void k_xstats(const float* __restrict__ x, int N) {
    float s0 = 0, s1 = 0, s2 = 0, q0 = 0, q1 = 0, q2 = 0, q3 = 0, q4 = 0, q5 = 0;
    int stride = gridDim.x * blockDim.x;
    for (int n = blockIdx.x * blockDim.x + threadIdx.x; n < N; n += stride) {
        float a = x[n], b = x[N + n], c = x[2 * N + n];
        s0 += a; s1 += b; s2 += c;
        q0 += a * a; q1 += a * b; q2 += a * c; q3 += b * b; q4 += b * c; q5 += c * c;
    }
    __shared__ float rb[256];
    float vals[9] = {s0, s1, s2, q0, q1, q2, q3, q4, q5};
    for (int v = 0; v < 9; v++) {
        rb[threadIdx.x] = vals[v];
        __syncthreads();
        for (int st = 128; st > 0; st >>= 1) {
            if (threadIdx.x < st) rb[threadIdx.x] += rb[threadIdx.x + st];
            __syncthreads();
        }
        if (threadIdx.x == 0) g_xpart[blockIdx.x * 9 + v] = rb[0];
        __syncthreads();
    }
}

// ---------------- K1b: fold BN1 into conv1a ----------------
__global__ void k_fold1(const float* __restrict__ W1a, const float* __restrict__ b1a,
                        const float* __restrict__ g1,  const float* __restrict__ be1,
                        int N, int nblocks) {
    __shared__ double S[9];
    __shared__ float mu[3], C[3][3];
    if (threadIdx.x < 9) {
        double a = 0;
        for (int b = 0; b < nblocks; b++) a += (double)g_xpart[b * 9 + threadIdx.x];
        S[threadIdx.x] = a;
    }
    __syncthreads();
    if (threadIdx.x == 0) {
        double invN = 1.0 / (double)N;
        double m0 = S[0] * invN, m1 = S[1] * invN, m2 = S[2] * invN;
        mu[0] = (float)m0; mu[1] = (float)m1; mu[2] = (float)m2;
        C[0][0] = (float)(S[3] * invN - m0 * m0);
        C[0][1] = (float)(S[4] * invN - m0 * m1);
        C[0][2] = (float)(S[5] * invN - m0 * m2);
        C[1][1] = (float)(S[6] * invN - m1 * m1);
        C[1][2] = (float)(S[7] * invN - m1 * m2);
        C[2][2] = (float)(S[8] * invN - m2 * m2);
        C[1][0] = C[0][1]; C[2][0] = C[0][2]; C[2][1] = C[1][2];
    }
    __syncthreads();
    int c = threadIdx.x;
    float w0 = W1a[c * 3], w1 = W1a[c * 3 + 1], w2 = W1a[c * 3 + 2];
    float mean1 = w0 * mu[0] + w1 * mu[1] + w2 * mu[2] + b1a[c];
    float var1 = w0 * w0 * C[0][0] + w1 * w1 * C[1][1] + w2 * w2 * C[2][2]
               + 2.f * (w0 * w1 * C[0][1] + w0 * w2 * C[0][2] + w1 * w2 * C[1][2]);
    float a = g1[c] * rsqrtf(var1 + EPSV);
    g_Wf1[c * 3 + 0] = a * w0;
    g_Wf1[c * 3 + 1] = a * w1;
    g_Wf1[c * 3 + 2] = a * w2;
    g_bf1[c] = a * (b1a[c] - mean1) + be1[c];
}

// ---------------- K2: fused conv1a+BN1+ReLU+conv1b + seg-max(pool1) ----------------
__global__ void __launch_bounds__(256) k_stage1(const float* __restrict__ x,
                                                const float* __restrict__ W1b,
                                                const float* __restrict__ b1b,
                                                int N, int B) {
    __shared__ float xs[3 * 64];
    __shared__ float hs[128 * 64];
    __shared__ int s_segA, s_bnd;
    int tid = threadIdx.x;
    int n0 = blockIdx.x * 64;
    if (tid < 192) xs[tid] = x[(tid >> 6) * N + n0 + (tid & 63)];
    if (tid == 0) {
        int s = 0;
        while (s + 1 < B && g_off[s + 1] <= n0) s++;
        s_segA = s; s_bnd = g_off[s + 1];
    }
    __syncthreads();
    #pragma unroll
    for (int i = 0; i < 32; i++) {
        int e = tid + i * 256;
        int c = e >> 6, p = e & 63;
        float h = g_bf1[c] + g_Wf1[c * 3] * xs[p]
                + g_Wf1[c * 3 + 1] * xs[64 + p]
                + g_Wf1[c * 3 + 2] * xs[128 + p];
        hs[e] = fmaxf(h, 0.f);
    }
    __syncthreads();
    float acc[64];
    #pragma unroll
    for (int p = 0; p < 64; p++) acc[p] = 0.f;
    const float* wrow = W1b + tid * 128;
    for (int k0 = 0; k0 < 128; k0 += 16) {
        float4 w4[4];
        w4[0] = *(const float4*)(wrow + k0);
        w4[1] = *(const float4*)(wrow + k0 + 4);
        w4[2] = *(const float4*)(wrow + k0 + 8);
        w4[3] = *(const float4*)(wrow + k0 + 12);
        const float* wv = (const float*)w4;
        #pragma unroll
        for (int kk = 0; kk < 16; kk++) {
            float w = wv[kk];
            const float4* hp = (const float4*)&hs[(k0 + kk) * 64];
            #pragma unroll
            for (int p4 = 0; p4 < 16; p4++) {
                float4 hv = hp[p4];
                acc[p4 * 4 + 0] += w * hv.x;
                acc[p4 * 4 + 1] += w * hv.y;
                acc[p4 * 4 + 2] += w * hv.z;
                acc[p4 * 4 + 3] += w * hv.w;
            }
        }
    }
    float bb = b1b[tid];
    float mA = -CUDART_INF_F, mB = -CUDART_INF_F;
    int bnd = s_bnd;
    __half* dst = &g_mlph[(size_t)tid * N + n0];
    #pragma unroll
    for (int p = 0; p < 64; p++) {
        float v = acc[p] + bb;
        acc[p] = v;
        if (n0 + p < bnd) mA = fmaxf(mA, v); else mB = fmaxf(mB, v);
    }
    #pragma unroll
    for (int p2 = 0; p2 < 32; p2++) {
        *(__half2*)&dst[p2 * 2] = __floats2half2_rn(acc[2 * p2], acc[2 * p2 + 1]);
    }
    atomicMax(&g_pool1u[s_segA * 256 + tid], fkey(mA));
    if (bnd < n0 + 64) atomicMax(&g_pool1u[(s_segA + 1) * 256 + tid], fkey(mB));
}

__global__ void k_decode1(int B) {
    int i = blockIdx.x * blockDim.x + threadIdx.x;
    if (i < B * 256) g_pool1h[i] = __float2half_rn(funkey(g_pool1u[i]));
}

// ---------------- tensor-core GEMMs ----------------
// MODE 0: y2 = W2a * [mlp;sym] + b2a, epilogue: store y2 fp16 + BN2 stat partials
// MODE 1: comb = W2b * relu(a2*y2+c2) + b2b, epilogue: fused segment max
// Tiles: 128 (c) x 256 (n) x 16 (k), 256 threads, warp = 64x64, m16n8k16 fp16 mma.
template<int MODE>
__global__ void __launch_bounds__(256) k_mma(const float* __restrict__ bias,
                                             int N, int B) {
    __shared__ __align__(16) __half As[2][128][24];
    __shared__ __align__(16) __half Bs[2][16][264];
    __shared__ float s_red[128][4];

    const int tid = threadIdx.x, lane = tid & 31, wid = tid >> 5;
    const int wm = wid & 1, wn = wid >> 1;
    const int quad = lane >> 2, qlane = lane & 3;
    const int n0 = blockIdx.x * 256;
    const int c0 = blockIdx.y * 128;

    const __half* __restrict__ Aw = (MODE == 0 ? g_W2a_h : g_W2b_h);
    const __half* AglobBase = Aw + (size_t)(c0 + (tid >> 1)) * 512 + (tid & 1) * 8;
    const int kloc = tid >> 4;
    const int ncol = n0 + (tid & 15) * 16;

    // smem addresses for ldmatrix (both buffers)
    unsigned aAddr[2][4], bAddr[2][4];
    #pragma unroll
    for (int s = 0; s < 2; s++) {
        unsigned aBase = smem_u32(&As[s][0][0]);
        unsigned bBase = smem_u32(&Bs[s][0][0]);
        #pragma unroll
        for (int mf = 0; mf < 4; mf++)
            aAddr[s][mf] = aBase + (((wm * 64 + mf * 16 + (lane & 15)) * 24
                                     + (lane >> 4) * 8) << 1);
        #pragma unroll
        for (int np = 0; np < 4; np++)
            bAddr[s][np] = bBase + (((lane & 15) * 264 + wn * 64 + np * 16
                                     + (lane >> 4) * 8) << 1);
    }

    float acc[4][8][4];
    #pragma unroll
    for (int m = 0; m < 4; m++)
        #pragma unroll
        for (int n = 0; n < 8; n++)
            #pragma unroll
            for (int v = 0; v < 4; v++) acc[m][n][v] = 0.f;

    // prefetch helpers
    uint4 pa, pb0, pb1;
    auto loadTiles = [&](int ks) {
        pa = *(const uint4*)(AglobBase + ks * 16);
        int krow = ks * 16 + kloc;
        if (MODE == 0) {
            if (krow < 256) {
                const uint4* p = (const uint4*)(g_mlph + (size_t)krow * N + ncol);
                pb0 = p[0]; pb1 = p[1];
            } else {
                union { __half h[16]; uint4 u[2]; } tb;
                const unsigned char* sp = g_segid + ncol;
                int cs = krow - 256;
                #pragma unroll
                for (int j = 0; j < 16; j++) tb.h[j] = g_pool1h[sp[j] * 256 + cs];
                pb0 = tb.u[0]; pb1 = tb.u[1];
            }
        } else {
            const uint4* p = (const uint4*)(g_y2h + (size_t)krow * N + ncol);
            union { __half h[16]; uint4 u[2]; } src, tb;
            src.u[0] = p[0]; src.u[1] = p[1];
            float a = g_a2[krow], cc = g_c2[krow];
            #pragma unroll
            for (int j = 0; j < 16; j++)
                tb.h[j] = __float2half_rn(fmaxf(__half2float(src.h[j]) * a + cc, 0.f));
            pb0 = tb.u[0]; pb1 = tb.u[1];
        }
    };
    auto storeTiles = [&](int s) {
        *(uint4*)&As[s][tid >> 1][(tid & 1) * 8] = pa;
        *(uint4*)&Bs[s][kloc][(tid & 15) * 16] = pb0;
        *(uint4*)&Bs[s][kloc][(tid & 15) * 16 + 8] = pb1;
    };

    loadTiles(0);
    storeTiles(0);
    __syncthreads();

    for (int ks = 0; ks < 32; ks++) {
        int cur = ks & 1;
        if (ks < 31) loadTiles(ks + 1);
        unsigned af[4][4], bf[4][4];
        #pragma unroll
        for (int mf = 0; mf < 4; mf++) ldsm_x4(af[mf], aAddr[cur][mf]);
        #pragma unroll
        for (int np = 0; np < 4; np++) ldsm_x4_t(bf[np], bAddr[cur][np]);
        #pragma unroll
        for (int mf = 0; mf < 4; mf++)
            #pragma unroll
            for (int nf = 0; nf < 8; nf++)
                mma16816(acc[mf][nf], af[mf], bf[nf >> 1][(nf & 1) * 2],
                         bf[nf >> 1][(nf & 1) * 2 + 1]);
        if (ks < 31) storeTiles(cur ^ 1);
        __syncthreads();
    }

    // ---------------- epilogues ----------------
    if (MODE == 0) {
        int nb = blockIdx.x;
        float sums[4][2], sqs[4][2];
        #pragma unroll
        for (int mf = 0; mf < 4; mf++) {
            int cA = c0 + wm * 64 + mf * 16 + quad;
            int cB = cA + 8;
            float bA = bias[cA], bB = bias[cB];
            float sA = 0, qA = 0, sB = 0, qB = 0;
            #pragma unroll
            for (int nf = 0; nf < 8; nf++) {
                int n = n0 + wn * 64 + nf * 8 + qlane * 2;
                float v0 = acc[mf][nf][0] + bA;
                float v1 = acc[mf][nf][1] + bA;
                float v2 = acc[mf][nf][2] + bB;
                float v3 = acc[mf][nf][3] + bB;
                *(__half2*)&g_y2h[(size_t)cA * N + n] = __floats2half2_rn(v0, v1);
                *(__half2*)&g_y2h[(size_t)cB * N + n] = __floats2half2_rn(v2, v3);
                sA += v0 + v1; qA += v0 * v0 + v1 * v1;
                sB += v2 + v3; qB += v2 * v2 + v3 * v3;
            }
            sums[mf][0] = sA; sums[mf][1] = sB;
            sqs[mf][0] = qA;  sqs[mf][1] = qB;
        }
        #pragma unroll
        for (int mf = 0; mf < 4; mf++)
            #pragma unroll
            for (int h = 0; h < 2; h++) {
                float v = sums[mf][h];
                v += __shfl_xor_sync(0xffffffff, v, 1);
                v += __shfl_xor_sync(0xffffffff, v, 2);
                if (qlane == 0) s_red[wm * 64 + mf * 16 + h * 8 + quad][wn] = v;
            }
        __syncthreads();
        if (tid < 128)
            g_psum[(size_t)(c0 + tid) * 512 + nb] =
                s_red[tid][0] + s_red[tid][1] + s_red[tid][2] + s_red[tid][3];
        __syncthreads();
        #pragma unroll
        for (int mf = 0; mf < 4; mf++)
            #pragma unroll
            for (int h = 0; h < 2; h++) {
                float v = sqs[mf][h];
                v += __shfl_xor_sync(0xffffffff, v, 1);
                v += __shfl_xor_sync(0xffffffff, v, 2);
                if (qlane == 0) s_red[wm * 64 + mf * 16 + h * 8 + quad][wn] = v;
            }
        __syncthreads();
        if (tid < 128)
            g_psq[(size_t)(c0 + tid) * 512 + nb] =
                s_red[tid][0] + s_red[tid][1] + s_red[tid][2] + s_red[tid][3];
    } else {
        __shared__ int s_seg, s_bnd;
        if (tid == 0) {
            int s = g_segid[n0];
            s_seg = s; s_bnd = g_off[s + 1];
        }
        __syncthreads();
        int bnd = s_bnd;
        bool hasB = (bnd < n0 + 256);
        float mA[4][2], mB[4][2];
        #pragma unroll
        for (int mf = 0; mf < 4; mf++) {
            int cA = c0 + wm * 64 + mf * 16 + quad;
            float bA = bias[cA], bB = bias[cA + 8];
            float a0 = -CUDART_INF_F, b0 = -CUDART_INF_F;
            float a1 = -CUDART_INF_F, b1 = -CUDART_INF_F;
            #pragma unroll
            for (int nf = 0; nf < 8; nf++) {
                int n = n0 + wn * 64 + nf * 8 + qlane * 2;
                float v0 = acc[mf][nf][0] + bA;
                float v1 = acc[mf][nf][1] + bA;
                float v2 = acc[mf][nf][2] + bB;
                float v3 = acc[mf][nf][3] + bB;
                if (n < bnd)     a0 = fmaxf(a0, v0); else b0 = fmaxf(b0, v0);
                if (n + 1 < bnd) a0 = fmaxf(a0, v1); else b0 = fmaxf(b0, v1);
                if (n < bnd)     a1 = fmaxf(a1, v2); else b1 = fmaxf(b1, v2);
                if (n + 1 < bnd) a1 = fmaxf(a1, v3); else b1 = fmaxf(b1, v3);
            }
            mA[mf][0] = a0; mA[mf][1] = a1;
            mB[mf][0] = b0; mB[mf][1] = b1;
        }
        #pragma unroll
        for (int mf = 0; mf < 4; mf++)
            #pragma unroll
            for (int h = 0; h < 2; h++) {
                float v = mA[mf][h];
                v = fmaxf(v, __shfl_xor_sync(0xffffffff, v, 1));
                v = fmaxf(v, __shfl_xor_sync(0xffffffff, v, 2));
                if (qlane == 0) s_red[wm * 64 + mf * 16 + h * 8 + quad][wn] = v;
            }
        __syncthreads();
        if (tid < 128) {
            float m = fmaxf(fmaxf(s_red[tid][0], s_red[tid][1]),
                            fmaxf(s_red[tid][2], s_red[tid][3]));
            atomicMax(&g_pool2u[s_seg * 1024 + c0 + tid], fkey(m));
        }
        __syncthreads();
        if (hasB) {
            #pragma unroll
            for (int mf = 0; mf < 4; mf++)
                #pragma unroll
                for (int h = 0; h < 2; h++) {
                    float v = mB[mf][h];
                    v = fmaxf(v, __shfl_xor_sync(0xffffffff, v, 1));
                    v = fmaxf(v, __shfl_xor_sync(0xffffffff, v, 2));
                    if (qlane == 0) s_red[wm * 64 + mf * 16 + h * 8 + quad][wn] = v;
                }
            __syncthreads();
            if (tid < 128) {
                float m = fmaxf(fmaxf(s_red[tid][0], s_red[tid][1]),
                                fmaxf(s_red[tid][2], s_red[tid][3]));
                atomicMax(&g_pool2u[(s_seg + 1) * 1024 + c0 + tid], fkey(m));
            }
        }
    }
}

// ---------------- K4: reduce BN2 stats ----------------
__global__ void k_bn2(const float* __restrict__ g2, const float* __restrict__ be2,
                      int N, int NB) {
    int c = blockIdx.x * blockDim.x + threadIdx.x;
    if (c >= 512) return;
    double s = 0, q = 0;
    for (int nb = 0; nb < NB; nb++) {
        s += (double)g_psum[(size_t)c * 512 + nb];
        q += (double)g_psq[(size_t)c * 512 + nb];
    }
    double mean = s / (double)N;
    double var  = q / (double)N - mean * mean;
    float a = g2[c] * rsqrtf((float)var + EPSV);
    g_a2[c] = a;
    g_c2[c] = be2[c] - (float)mean * a;
}

// ---------------- K6: decode output ----------------
__global__ void k_out(float* __restrict__ out, int B) {
    int i = blockIdx.x * blockDim.x + threadIdx.x;
    if (i < B * 1024) out[i] = funkey(g_pool2u[i]);
}

// ---------------- launch ----------------
extern "C" void kernel_launch(void* const* d_in, const int* in_sizes, int n_in,
                              void* d_out, int out_size) {
    const float* x   = (const float*)d_in[0];
    const int*   np  = (const int*)  d_in[1];
    const float* W1a = (const float*)d_in[2];
    const float* b1a = (const float*)d_in[3];
    const float* g1  = (const float*)d_in[4];
    const float* be1 = (const float*)d_in[5];
    const float* W1b = (const float*)d_in[6];
    const float* b1b = (const float*)d_in[7];
    const float* W2a = (const float*)d_in[8];
    const float* b2a = (const float*)d_in[9];
    const float* g2  = (const float*)d_in[10];
    const float* be2 = (const float*)d_in[11];
    const float* W2b = (const float*)d_in[12];
    const float* b2b = (const float*)d_in[13];
    int N = in_sizes[0] / 3;
    int B = in_sizes[1];
    if (N > MAXN) N = MAXN;

    k_init<<<32, 256>>>(np, B);
    k_segid<<<(N + 255) / 256, 256>>>(N, B);
    k_convW<<<2048, 256>>>(W2a, W2b);
    k_xstats<<<128, 256>>>(x, N);
    k_fold1<<<1, 128>>>(W1a, b1a, g1, be1, N, 128);
    k_stage1<<<N / 64, 256>>>(x, W1b, b1b, N, B);
    k_decode1<<<(B * 256 + 255) / 256, 256>>>(B);
    dim3 g3(N / 256, 4);
    k_mma<0><<<g3, 256>>>(b2a, N, B);
    k_bn2<<<2, 256>>>(g2, be2, N, N / 256);
    dim3 g5(N / 256, 8);
    k_mma<1><<<g5, 256>>>(b2b, N, B);
    k_out<<<(B * 1024 + 255) / 256, 256>>>((float*)d_out, B);
}